// round 16
// baseline (speedup 1.0000x reference)
#include <cuda_runtime.h>
#include <cuda_bf16.h>
#include <math.h>

#define Bz   32
#define NMz  131072
#define Pz   256
#define Fz   3
#define Ez   64
#define Hz   4
#define Kz   3

#define NCHUNK 32
#define CHSZ   4096

#define FINF 3.402823466e+38f

// packed f32x2 helpers (two independent fp32 FMAs, bitwise == scalar FFMA)
#define FFMA2(d, a, b, c) \
  asm("fma.rn.f32x2 %0, %1, %2, %3;" : "=l"(d) : "l"(a), "l"(b), "l"(c))
#define PACKF2(d, x) \
  asm("mov.b64 %0, {%1, %1};" : "=l"(d) : "f"(x))
#define UNPACKF2(lo, hi, d) \
  asm("mov.b64 {%0, %1}, %2;" : "=f"(lo), "=f"(hi) : "l"(d))

// ---------------- device scratch ----------------
__device__ float  g_part_d[Pz * NCHUNK * Kz];
__device__ int    g_part_i[Pz * NCHUNK * Kz];
__device__ float  g_comp[128 * 8];       // per e: ca0,ca1,ca2,cb0,cb1,cc,_,_
__device__ float  g_y2c[3 * Bz * Pz];    // y2 as 3 scalar planes [f][b][p]
__device__ int4   g_k2i[NMz];            // knn2: 3 pivot indices (+pad)
__device__ float4 g_k2w[NMz];            // knn2: 3 normalized weights (+pad)

__device__ __forceinline__ void ins3lex(float d, int i,
    float &d0, int &i0, float &d1, int &i1, float &d2, int &i2) {
  if (d < d2 || (d == d2 && i < i2)) {
    if (d < d1 || (d == d1 && i < i1)) {
      d2 = d1; i2 = i1;
      if (d < d0 || (d == d0 && i < i0)) { d1 = d0; i1 = i0; d0 = d; i0 = i; }
      else                               { d1 = d;  i1 = i; }
    } else { d2 = d; i2 = i; }
  }
}

// ---------------- kernel 1: knn1 partials + knn2 + compose (one wave) ------
__global__ void __launch_bounds__(256) knn_all(
                             const float* __restrict__ pos_mesh,
                             const float* __restrict__ pos_piv,
                             const float* __restrict__ Wf,
                             const float* __restrict__ bf,
                             const float* __restrict__ Wp,
                             const float* __restrict__ bp,
                             const float* __restrict__ inW,
                             const float* __restrict__ inB) {
  extern __shared__ char smraw[];
  int blk = blockIdx.x;
  int t = threadIdx.x;

  if (blk < 256) {
    // ---- knn1 partial ----
    float2* pts = (float2*)smraw;                       // 4096 float2
    float*  smd = (float*)(smraw + CHSZ * 8);           // 256*3
    int*    smi = (int*)(smraw + CHSZ * 8 + 3072);      // 256*3
    int chunk = blk >> 3, pg = blk & 7;
    int base = chunk * CHSZ;
    const float2* pm2 = (const float2*)pos_mesh;
    for (int i = t; i < CHSZ; i += 256) pts[i] = pm2[base + i];
    __syncthreads();

    int pl  = t & 31, sub = t >> 5;
    int p   = pg * 32 + pl;
    float ppx = pos_piv[2 * p], ppy = pos_piv[2 * p + 1];

    float d0 = FINF, d1 = FINF, d2 = FINF;
    int   i0 = -1,  i1 = -1,  i2 = -1;
    int jbeg = sub * (CHSZ / 8), jend = jbeg + (CHSZ / 8);
    #pragma unroll 4
    for (int j = jbeg; j < jend; j++) {
      float2 m = pts[j];
      float dx = ppx - m.x, dy = ppy - m.y;
      float dd = dx * dx + dy * dy;
      if (dd < d2) {
        int gi = base + j;
        if (dd < d1) {
          d2 = d1; i2 = i1;
          if (dd < d0) { d1 = d0; i1 = i0; d0 = dd; i0 = gi; }
          else         { d1 = dd; i1 = gi; }
        } else { d2 = dd; i2 = gi; }
      }
    }
    smd[t*3+0] = d0; smd[t*3+1] = d1; smd[t*3+2] = d2;
    smi[t*3+0] = i0; smi[t*3+1] = i1; smi[t*3+2] = i2;
    __syncthreads();

    if (t < 32) {
      float b0 = FINF, b1 = FINF, b2 = FINF; int j0 = -1, j1 = -1, j2 = -1;
      for (int s = 0; s < 8; s++) {
        int e = (s * 32 + t) * 3;
        ins3lex(smd[e+0], smi[e+0], b0, j0, b1, j1, b2, j2);
        ins3lex(smd[e+1], smi[e+1], b0, j0, b1, j1, b2, j2);
        ins3lex(smd[e+2], smi[e+2], b0, j0, b1, j1, b2, j2);
      }
      int pp = pg * 32 + t;
      int o = (pp * NCHUNK + chunk) * 3;
      g_part_d[o+0] = b0; g_part_d[o+1] = b1; g_part_d[o+2] = b2;
      g_part_i[o+0] = j0; g_part_i[o+1] = j1; g_part_i[o+2] = j2;
    }
  } else if (blk < 768) {
    // ---- knn2: one mesh point per thread ----
    float2* pv = (float2*)smraw;    // 256
    if (t < 256) pv[t] = ((const float2*)pos_piv)[t];
    __syncthreads();
    int m = (blk - 256) * 256 + t;
    float2 mp = ((const float2*)pos_mesh)[m];
    float d0 = FINF, d1 = FINF, d2 = FINF;
    int   j0 = 0,   j1 = 0,   j2 = 0;
    #pragma unroll 4
    for (int j = 0; j < 256; j++) {
      float2 pp = pv[j];
      float dx = mp.x - pp.x, dy = mp.y - pp.y;
      float dd = dx * dx + dy * dy;
      if (dd < d2) {
        if (dd < d1) {
          d2 = d1; j2 = j1;
          if (dd < d0) { d1 = d0; j1 = j0; d0 = dd; j0 = j; }
          else         { d1 = dd; j1 = j; }
        } else { d2 = dd; j2 = j; }
      }
    }
    float w0 = 1.f / fmaxf(d0, 1e-16f);
    float w1 = 1.f / fmaxf(d1, 1e-16f);
    float w2 = 1.f / fmaxf(d2, 1e-16f);
    float inv = 1.f / (w0 + w1 + w2);
    g_k2i[m] = make_int4(j0, j1, j2, 0);
    g_k2w[m] = make_float4(w0 * inv, w1 * inv, w2 * inv, 0.f);
  } else {
    // ---- compose ----
    int e = t;
    if (e < 128) {
      float ca0=0.f, ca1=0.f, ca2=0.f, cb0=0.f, cb1=0.f, cc=0.f;
      for (int d = 0; d < 64; d++) {
        float w = inW[e * 64 + d];
        ca0 += w * Wf[d*3+0];
        ca1 += w * Wf[d*3+1];
        ca2 += w * Wf[d*3+2];
        cb0 += w * Wp[d*2+0];
        cb1 += w * Wp[d*2+1];
        cc  += w * (bf[d] + bp[d]);
      }
      cc += inB[e];
      g_comp[e*8+0] = ca0; g_comp[e*8+1] = ca1; g_comp[e*8+2] = ca2;
      g_comp[e*8+3] = cb0; g_comp[e*8+4] = cb1; g_comp[e*8+5] = cc;
      g_comp[e*8+6] = 0.f; g_comp[e*8+7] = 0.f;
    }
  }
}

// ---------------- kernel 2: inline-merge + gather+ln + QK + attn + y2 ------
// grid 512 = (b, 16-query tile), 256 threads. Thread t = pivot t: redoes the
// cheap 32-chunk top-3 merge (L1/L2-resident, latency hidden at 512 blocks),
// then gather+layernorm, then the R12 attention body.
__global__ void __launch_bounds__(256, 3) attn_kernel(
                            const float* __restrict__ piv,
                            const float* __restrict__ na,
                            const float* __restrict__ gamma,
                            const float* __restrict__ beta) {
  __shared__ float  KTsh[32 * 256];   // one 32-e half of K^T
  __shared__ float  QTsh[64 * 16];
  __shared__ float  ysh[256 * 4];
  __shared__ float2 pvsh[256];
  __shared__ float  csh[128 * 8];
  __shared__ float  red[128];

  int blk = blockIdx.x;
  int b = blk >> 4, it = blk & 15;
  int i0 = it * 16;
  int t = threadIdx.x;

  // ---- inline knn1 merge for pivot p = t ----
  float mw0, mw1, mw2;
  int   mi0, mi1, mi2;
  {
    float b0 = FINF, b1 = FINF, b2 = FINF; int j0 = -1, j1 = -1, j2 = -1;
    #pragma unroll 4
    for (int c = 0; c < NCHUNK; c++) {
      int o = (t * NCHUNK + c) * 3;
      ins3lex(g_part_d[o+0], g_part_i[o+0], b0, j0, b1, j1, b2, j2);
      ins3lex(g_part_d[o+1], g_part_i[o+1], b0, j0, b1, j1, b2, j2);
      ins3lex(g_part_d[o+2], g_part_i[o+2], b0, j0, b1, j1, b2, j2);
    }
    float w0 = 1.f / fmaxf(b0, 1e-16f);
    float w1 = 1.f / fmaxf(b1, 1e-16f);
    float w2 = 1.f / fmaxf(b2, 1e-16f);
    float inv = 1.f / (w0 + w1 + w2);
    mw0 = w0 * inv; mw1 = w1 * inv; mw2 = w2 * inv;
    mi0 = j0; mi1 = j1; mi2 = j2;
  }

  // ---- gather + layernorm for pivot p = t ----
  float y0, y1, y2v;
  {
    int   idx[3] = {mi0, mi1, mi2};
    float ww[3]  = {mw0, mw1, mw2};
    float g0 = gamma[0], g1 = gamma[1], g2 = gamma[2];
    float e0 = beta[0],  e1 = beta[1],  e2b = beta[2];
    float a0 = 0.f, a1 = 0.f, a2 = 0.f;
    #pragma unroll
    for (int k = 0; k < 3; k++) {
      const float* xr = na + ((long)b * NMz + idx[k]) * 3;
      float x0 = xr[0], x1 = xr[1], x2 = xr[2];
      float mu = (x0 + x1 + x2) * (1.0f / 3.0f);
      float c0 = x0 - mu, c1 = x1 - mu, c2 = x2 - mu;
      float var = (c0*c0 + c1*c1 + c2*c2) * (1.0f / 3.0f);
      float r = rsqrtf(var + 1e-5f);
      a0 += ww[k] * (c0 * r * g0 + e0);
      a1 += ww[k] * (c1 * r * g1 + e1);
      a2 += ww[k] * (c2 * r * g2 + e2b);
    }
    y0 = a0; y1 = a1; y2v = a2;
    ysh[t*4+0] = y0; ysh[t*4+1] = y1; ysh[t*4+2] = y2v; ysh[t*4+3] = 0.f;
    pvsh[t] = ((const float2*)piv)[t];
  }
  for (int idx = t; idx < 1024; idx += 256) csh[idx] = g_comp[idx];
  __syncthreads();

  float2 ppt = pvsh[t];
  // ---- K build, half A: e = 0..31 (comp rows 64..95) ----
  #pragma unroll 4
  for (int e = 0; e < 32; e++) {
    float4 c0 = *(const float4*)&csh[(64 + e) * 8];
    float4 c1 = *(const float4*)&csh[(64 + e) * 8 + 4];
    KTsh[e * 256 + t] = c1.y + c0.x*y0 + c0.y*y1 + c0.z*y2v
                      + c0.w*ppt.x + c1.x*ppt.y;
  }
  // ---- Q build: all 64 e ----
  {
    int qi = t & 15, eb = t >> 4;
    int i = i0 + qi;
    float qy0 = ysh[i*4], qy1 = ysh[i*4+1], qy2 = ysh[i*4+2];
    float2 qp = pvsh[i];
    #pragma unroll
    for (int k = 0; k < 4; k++) {
      int e = eb * 4 + k;
      float4 c0 = *(const float4*)&csh[e * 8];
      float4 c1 = *(const float4*)&csh[e * 8 + 4];
      QTsh[e * 16 + qi] = c1.y + c0.x*qy0 + c0.y*qy1 + c0.z*qy2
                        + c0.w*qp.x + c1.x*qp.y;
    }
  }
  __syncthreads();

  int tj = t & 63, ig = t >> 6, warp = t >> 5;
  float4 yv[4];
  #pragma unroll
  for (int jl = 0; jl < 4; jl++)
    yv[jl] = *(const float4*)&ysh[(4 * tj + jl) * 4];
  float p2[4][3];
  #pragma unroll
  for (int ir = 0; ir < 4; ir++) { p2[ir][0]=0.f; p2[ir][1]=0.f; p2[ir][2]=0.f; }

  #pragma unroll
  for (int hh = 0; hh < 4; hh++) {
    if (hh == 2) {
      __syncthreads();
      #pragma unroll 4
      for (int e = 0; e < 32; e++) {     // half B: e = 32..63 (rows 96..127)
        float4 c0 = *(const float4*)&csh[(96 + e) * 8];
        float4 c1 = *(const float4*)&csh[(96 + e) * 8 + 4];
        KTsh[e * 256 + t] = c1.y + c0.x*y0 + c0.y*y1 + c0.z*y2v
                          + c0.w*ppt.x + c1.x*ppt.y;
      }
      __syncthreads();
    }
    int ebase = hh * 16;
    int krow  = (hh & 1) * 16;

    // packed accumulators: a2[ir][0] = {jl0, jl1}, a2[ir][1] = {jl2, jl3}
    unsigned long long a2[4][2];
    #pragma unroll
    for (int a = 0; a < 4; a++) { a2[a][0] = 0ull; a2[a][1] = 0ull; }

    #pragma unroll
    for (int d = 0; d < 16; d++) {
      const ulonglong2 kvp =
          *(const ulonglong2*)&KTsh[(krow + d) * 256 + 4 * tj];
      const float4 qv = *(const float4*)&QTsh[(ebase + d) * 16 + 4 * ig];
      unsigned long long q;
      PACKF2(q, qv.x);
      FFMA2(a2[0][0], q, kvp.x, a2[0][0]); FFMA2(a2[0][1], q, kvp.y, a2[0][1]);
      PACKF2(q, qv.y);
      FFMA2(a2[1][0], q, kvp.x, a2[1][0]); FFMA2(a2[1][1], q, kvp.y, a2[1][1]);
      PACKF2(q, qv.z);
      FFMA2(a2[2][0], q, kvp.x, a2[2][0]); FFMA2(a2[2][1], q, kvp.y, a2[2][1]);
      PACKF2(q, qv.w);
      FFMA2(a2[3][0], q, kvp.x, a2[3][0]); FFMA2(a2[3][1], q, kvp.y, a2[3][1]);
    }

    float acc[4][4];
    #pragma unroll
    for (int ir = 0; ir < 4; ir++) {
      UNPACKF2(acc[ir][0], acc[ir][1], a2[ir][0]);
      UNPACKF2(acc[ir][2], acc[ir][3], a2[ir][1]);
    }

    float sv[4];
    #pragma unroll
    for (int ir = 0; ir < 4; ir++) {
      float s = 0.f;
      #pragma unroll
      for (int jl = 0; jl < 4; jl++) {
        acc[ir][jl] = __expf(acc[ir][jl] * 0.25f);
        s += acc[ir][jl];
      }
      #pragma unroll
      for (int o = 16; o; o >>= 1)
        s += __shfl_xor_sync(0xffffffffu, s, o);
      sv[ir] = s;
    }
    if ((t & 31) == 0) {
      #pragma unroll
      for (int ir = 0; ir < 4; ir++) red[hh*32 + warp*4 + ir] = sv[ir];
    }
    __syncthreads();
    #pragma unroll
    for (int ir = 0; ir < 4; ir++)
      sv[ir] = 0.25f / (red[hh*32 + (ig*2)*4 + ir]
                      + red[hh*32 + (ig*2+1)*4 + ir]);

    #pragma unroll
    for (int ir = 0; ir < 4; ir++) {
      #pragma unroll
      for (int jl = 0; jl < 4; jl++) {
        float aw = acc[ir][jl] * sv[ir];
        p2[ir][0] += aw * yv[jl].x;
        p2[ir][1] += aw * yv[jl].y;
        p2[ir][2] += aw * yv[jl].z;
      }
    }
  }

  // ---- final reduction of p2 over the 64-group ----
  #pragma unroll
  for (int ir = 0; ir < 4; ir++)
    #pragma unroll
    for (int f = 0; f < 3; f++) {
      float v = p2[ir][f];
      #pragma unroll
      for (int o = 16; o; o >>= 1)
        v += __shfl_xor_sync(0xffffffffu, v, o);
      p2[ir][f] = v;
    }
  __syncthreads();
  if ((t & 31) == 0) {
    #pragma unroll
    for (int ir = 0; ir < 4; ir++)
      #pragma unroll
      for (int f = 0; f < 3; f++) red[warp * 16 + ir*3 + f] = p2[ir][f];
  }
  __syncthreads();
  if (tj == 0) {
    int w0 = (ig * 2) * 16, w1 = (ig * 2 + 1) * 16;
    #pragma unroll
    for (int ir = 0; ir < 4; ir++) {
      int i = i0 + ig * 4 + ir;
      #pragma unroll
      for (int f = 0; f < 3; f++)
        g_y2c[(f * Bz + b) * Pz + i] = red[w0 + ir*3 + f] + red[w1 + ir*3 + f];
    }
  }
}

// ---------------- kernel 3: interp + 50MB write (3 scalar planes) ----------
// grid (NMz/256, 4); block stages 8 batches x 3 planes (24 KB smem).
__global__ void __launch_bounds__(256) out_kernel(float* __restrict__ out) {
  __shared__ float y2sh[3][8 * 256];
  int t = threadIdx.x;
  int bg = blockIdx.y;          // batch group: 8 batches
  #pragma unroll
  for (int c = 0; c < 3; c++) {
    const float4* src = (const float4*)(g_y2c + (c * Bz + bg * 8) * Pz);
    #pragma unroll
    for (int k = 0; k < 2; k++)
      ((float4*)y2sh[c])[k * 256 + t] = src[k * 256 + t];
  }
  __syncthreads();

  int m = blockIdx.x * 256 + t;
  int4   ji = g_k2i[m];
  float4 wv = g_k2w[m];
  float w0 = wv.x, w1 = wv.y, w2 = wv.z;

  #pragma unroll
  for (int b = 0; b < 8; b++) {
    int o = b * 256;
    float r0 = w0*y2sh[0][o+ji.x] + w1*y2sh[0][o+ji.y] + w2*y2sh[0][o+ji.z];
    float r1 = w0*y2sh[1][o+ji.x] + w1*y2sh[1][o+ji.y] + w2*y2sh[1][o+ji.z];
    float r2 = w0*y2sh[2][o+ji.x] + w1*y2sh[2][o+ji.y] + w2*y2sh[2][o+ji.z];
    float* op = out + ((long)(bg * 8 + b) * NMz + m) * 3;
    op[0] = r0; op[1] = r1; op[2] = r2;
  }
}

// ---------------- launch ---------------------------------------------------
extern "C" void kernel_launch(void* const* d_in, const int* in_sizes, int n_in,
                              void* d_out, int out_size) {
  const float* node_attr = (const float*)d_in[0];
  const float* pos_mesh  = (const float*)d_in[1];
  const float* pos_piv   = (const float*)d_in[2];
  const float* gamma     = (const float*)d_in[3];
  const float* beta      = (const float*)d_in[4];
  const float* Wf        = (const float*)d_in[5];
  const float* bf        = (const float*)d_in[6];
  const float* Wp        = (const float*)d_in[7];
  const float* bp        = (const float*)d_in[8];
  const float* inW       = (const float*)d_in[9];
  const float* inB       = (const float*)d_in[10];
  float* out = (float*)d_out;

  const int SMEM_KNN = CHSZ * 8 + 2 * 3072;        // 38,912 B
  cudaFuncSetAttribute(knn_all,
      cudaFuncAttributeMaxDynamicSharedMemorySize, SMEM_KNN);

  knn_all<<<769, 256, SMEM_KNN>>>(pos_mesh, pos_piv,
                                  Wf, bf, Wp, bp, inW, inB);
  attn_kernel<<<512, 256>>>(pos_piv, node_attr, gamma, beta);
  out_kernel<<<dim3(NMz / 256, 4), 256>>>(out);
}

// round 17
// speedup vs baseline: 1.6696x; 1.6696x over previous
#include <cuda_runtime.h>
#include <cuda_bf16.h>
#include <math.h>

#define Bz   32
#define NMz  131072
#define Pz   256
#define Fz   3
#define Ez   64
#define Hz   4
#define Kz   3

#define NCHUNK 32
#define CHSZ   4096

#define FINF 3.402823466e+38f

// packed f32x2 helpers (two independent fp32 FMAs, bitwise == scalar FFMA)
#define FFMA2(d, a, b, c) \
  asm("fma.rn.f32x2 %0, %1, %2, %3;" : "=l"(d) : "l"(a), "l"(b), "l"(c))
#define PACKF2(d, x) \
  asm("mov.b64 %0, {%1, %1};" : "=l"(d) : "f"(x))
#define UNPACKF2(lo, hi, d) \
  asm("mov.b64 {%0, %1}, %2;" : "=f"(lo), "=f"(hi) : "l"(d))

// ---------------- device scratch ----------------
__device__ int    g_idx1[Pz * Kz];
__device__ float  g_w1[Pz * Kz];
__device__ float  g_part_d[Pz * NCHUNK * Kz];
__device__ int    g_part_i[Pz * NCHUNK * Kz];
__device__ float  g_comp[128 * 8];       // per e: ca0,ca1,ca2,cb0,cb1,cc,_,_
__device__ float  g_y2c[3 * Bz * Pz];    // y2 as 3 scalar planes [f][b][p]
__device__ int4   g_k2i[NMz];            // knn2: 3 pivot indices (+pad)
__device__ float4 g_k2w[NMz];            // knn2: 3 normalized weights (+pad)

__device__ __forceinline__ void ins3lex(float d, int i,
    float &d0, int &i0, float &d1, int &i1, float &d2, int &i2) {
  if (d < d2 || (d == d2 && i < i2)) {
    if (d < d1 || (d == d1 && i < i1)) {
      d2 = d1; i2 = i1;
      if (d < d0 || (d == d0 && i < i0)) { d1 = d0; i1 = i0; d0 = d; i0 = i; }
      else                               { d1 = d;  i1 = i; }
    } else { d2 = d; i2 = i; }
  }
}

// branchy strict-< insert (ascending scan keeps earliest index on ties)
__device__ __forceinline__ void ins3(float dd, int gi,
    float &d0, int &i0, float &d1, int &i1, float &d2, int &i2) {
  if (dd < d2) {
    if (dd < d1) {
      d2 = d1; i2 = i1;
      if (dd < d0) { d1 = d0; i1 = i0; d0 = dd; i0 = gi; }
      else         { d1 = dd; i1 = gi; }
    } else { d2 = dd; i2 = gi; }
  }
}

// ---------------- kernel 1: knn1 partials + knn2 + compose (one wave) ------
__global__ void __launch_bounds__(256) knn_all(
                             const float* __restrict__ pos_mesh,
                             const float* __restrict__ pos_piv,
                             const float* __restrict__ Wf,
                             const float* __restrict__ bf,
                             const float* __restrict__ Wp,
                             const float* __restrict__ bp,
                             const float* __restrict__ inW,
                             const float* __restrict__ inB) {
  extern __shared__ char smraw[];
  int blk = blockIdx.x;
  int t = threadIdx.x;

  if (blk < 256) {
    // ---- knn1 partial: pts staged as float4 (2 candidates per 16B) ----
    float4* pts4 = (float4*)smraw;                      // 2048 float4 = 32 KB
    float*  smd = (float*)(smraw + CHSZ * 8);           // 256*3
    int*    smi = (int*)(smraw + CHSZ * 8 + 3072);      // 256*3
    int chunk = blk >> 3, pg = blk & 7;
    int base = chunk * CHSZ;
    const float4* pm4 = (const float4*)(pos_mesh + 2 * base);
    #pragma unroll
    for (int i = 0; i < 8; i++) pts4[i * 256 + t] = pm4[i * 256 + t];
    __syncthreads();

    int pl  = t & 31, sub = t >> 5;
    int p   = pg * 32 + pl;
    float ppx = pos_piv[2 * p], ppy = pos_piv[2 * p + 1];

    float d0 = FINF, d1 = FINF, d2 = FINF;
    int   i0 = -1,  i1 = -1,  i2 = -1;
    // each sub handles 512 candidates = 256 float4 iterations
    const float4* pw = pts4 + sub * 256;
    int gibase = base + sub * 512;
    #pragma unroll 8
    for (int j = 0; j < 256; j++) {
      float4 c = pw[j];
      float dx0 = ppx - c.x, dy0 = ppy - c.y;
      float dd0 = dx0 * dx0 + dy0 * dy0;
      float dx1 = ppx - c.z, dy1 = ppy - c.w;
      float dd1 = dx1 * dx1 + dy1 * dy1;
      ins3(dd0, gibase + 2 * j,     d0, i0, d1, i1, d2, i2);
      ins3(dd1, gibase + 2 * j + 1, d0, i0, d1, i1, d2, i2);
    }
    smd[t*3+0] = d0; smd[t*3+1] = d1; smd[t*3+2] = d2;
    smi[t*3+0] = i0; smi[t*3+1] = i1; smi[t*3+2] = i2;
    __syncthreads();

    if (t < 32) {
      float b0 = FINF, b1 = FINF, b2 = FINF; int j0 = -1, j1 = -1, j2 = -1;
      for (int s = 0; s < 8; s++) {
        int e = (s * 32 + t) * 3;
        ins3lex(smd[e+0], smi[e+0], b0, j0, b1, j1, b2, j2);
        ins3lex(smd[e+1], smi[e+1], b0, j0, b1, j1, b2, j2);
        ins3lex(smd[e+2], smi[e+2], b0, j0, b1, j1, b2, j2);
      }
      int pp = pg * 32 + t;
      int o = (pp * NCHUNK + chunk) * 3;
      g_part_d[o+0] = b0; g_part_d[o+1] = b1; g_part_d[o+2] = b2;
      g_part_i[o+0] = j0; g_part_i[o+1] = j1; g_part_i[o+2] = j2;
    }
  } else if (blk < 768) {
    // ---- knn2: pivots staged as float4 (2 pivots per 16B), broadcast ----
    float4* pv4 = (float4*)smraw;    // 128 float4
    if (t < 128) pv4[t] = ((const float4*)pos_piv)[t];
    __syncthreads();
    int m = (blk - 256) * 256 + t;
    float2 mp = ((const float2*)pos_mesh)[m];
    float d0 = FINF, d1 = FINF, d2 = FINF;
    int   j0 = 0,   j1 = 0,   j2 = 0;
    #pragma unroll 8
    for (int j = 0; j < 128; j++) {
      float4 c = pv4[j];
      float dx0 = mp.x - c.x, dy0 = mp.y - c.y;
      float dd0 = dx0 * dx0 + dy0 * dy0;
      float dx1 = mp.x - c.z, dy1 = mp.y - c.w;
      float dd1 = dx1 * dx1 + dy1 * dy1;
      ins3(dd0, 2 * j,     d0, j0, d1, j1, d2, j2);
      ins3(dd1, 2 * j + 1, d0, j0, d1, j1, d2, j2);
    }
    float w0 = 1.f / fmaxf(d0, 1e-16f);
    float w1 = 1.f / fmaxf(d1, 1e-16f);
    float w2 = 1.f / fmaxf(d2, 1e-16f);
    float inv = 1.f / (w0 + w1 + w2);
    g_k2i[m] = make_int4(j0, j1, j2, 0);
    g_k2w[m] = make_float4(w0 * inv, w1 * inv, w2 * inv, 0.f);
  } else {
    // ---- compose ----
    int e = t;
    if (e < 128) {
      float ca0=0.f, ca1=0.f, ca2=0.f, cb0=0.f, cb1=0.f, cc=0.f;
      for (int d = 0; d < 64; d++) {
        float w = inW[e * 64 + d];
        ca0 += w * Wf[d*3+0];
        ca1 += w * Wf[d*3+1];
        ca2 += w * Wf[d*3+2];
        cb0 += w * Wp[d*2+0];
        cb1 += w * Wp[d*2+1];
        cc  += w * (bf[d] + bp[d]);
      }
      cc += inB[e];
      g_comp[e*8+0] = ca0; g_comp[e*8+1] = ca1; g_comp[e*8+2] = ca2;
      g_comp[e*8+3] = cb0; g_comp[e*8+4] = cb1; g_comp[e*8+5] = cc;
      g_comp[e*8+6] = 0.f; g_comp[e*8+7] = 0.f;
    }
  }
}

// ---------------- kernel 2: knn1 final merge + weights ---------------------
__global__ void merge_kernel() {
  int p = threadIdx.x;
  float b0 = FINF, b1 = FINF, b2 = FINF; int j0 = -1, j1 = -1, j2 = -1;
  for (int c = 0; c < NCHUNK; c++) {
    int o = (p * NCHUNK + c) * 3;
    ins3lex(g_part_d[o+0], g_part_i[o+0], b0, j0, b1, j1, b2, j2);
    ins3lex(g_part_d[o+1], g_part_i[o+1], b0, j0, b1, j1, b2, j2);
    ins3lex(g_part_d[o+2], g_part_i[o+2], b0, j0, b1, j1, b2, j2);
  }
  float w0 = 1.f / fmaxf(b0, 1e-16f);
  float w1 = 1.f / fmaxf(b1, 1e-16f);
  float w2 = 1.f / fmaxf(b2, 1e-16f);
  float inv = 1.f / (w0 + w1 + w2);
  g_w1[p*3+0] = w0 * inv; g_w1[p*3+1] = w1 * inv; g_w1[p*3+2] = w2 * inv;
  g_idx1[p*3+0] = j0; g_idx1[p*3+1] = j1; g_idx1[p*3+2] = j2;
}

// ---------------- kernel 3: gather+ln + QK on-the-fly + attn + y2 ----------
__global__ void __launch_bounds__(256, 3) attn_kernel(
                            const float* __restrict__ piv,
                            const float* __restrict__ na,
                            const float* __restrict__ gamma,
                            const float* __restrict__ beta) {
  __shared__ float  KTsh[32 * 256];   // one 32-e half of K^T
  __shared__ float  QTsh[64 * 16];
  __shared__ float  ysh[256 * 4];
  __shared__ float2 pvsh[256];
  __shared__ float  csh[128 * 8];
  __shared__ float  red[128];

  int blk = blockIdx.x;
  int b = blk >> 4, it = blk & 15;
  int i0 = it * 16;
  int t = threadIdx.x;

  // ---- gather + layernorm for pivot p = t ----
  float y0, y1, y2v;
  {
    float g0 = gamma[0], g1 = gamma[1], g2 = gamma[2];
    float e0 = beta[0],  e1 = beta[1],  e2b = beta[2];
    float a0 = 0.f, a1 = 0.f, a2 = 0.f;
    #pragma unroll
    for (int k = 0; k < 3; k++) {
      int i = g_idx1[t*3+k];
      float w = g_w1[t*3+k];
      const float* xr = na + ((long)b * NMz + i) * 3;
      float x0 = xr[0], x1 = xr[1], x2 = xr[2];
      float mu = (x0 + x1 + x2) * (1.0f / 3.0f);
      float c0 = x0 - mu, c1 = x1 - mu, c2 = x2 - mu;
      float var = (c0*c0 + c1*c1 + c2*c2) * (1.0f / 3.0f);
      float r = rsqrtf(var + 1e-5f);
      a0 += w * (c0 * r * g0 + e0);
      a1 += w * (c1 * r * g1 + e1);
      a2 += w * (c2 * r * g2 + e2b);
    }
    y0 = a0; y1 = a1; y2v = a2;
    ysh[t*4+0] = y0; ysh[t*4+1] = y1; ysh[t*4+2] = y2v; ysh[t*4+3] = 0.f;
    pvsh[t] = ((const float2*)piv)[t];
  }
  for (int idx = t; idx < 1024; idx += 256) csh[idx] = g_comp[idx];
  __syncthreads();

  float2 ppt = pvsh[t];
  // ---- K build, half A: e = 0..31 (comp rows 64..95) ----
  #pragma unroll 4
  for (int e = 0; e < 32; e++) {
    float4 c0 = *(const float4*)&csh[(64 + e) * 8];
    float4 c1 = *(const float4*)&csh[(64 + e) * 8 + 4];
    KTsh[e * 256 + t] = c1.y + c0.x*y0 + c0.y*y1 + c0.z*y2v
                      + c0.w*ppt.x + c1.x*ppt.y;
  }
  // ---- Q build: all 64 e ----
  {
    int qi = t & 15, eb = t >> 4;
    int i = i0 + qi;
    float qy0 = ysh[i*4], qy1 = ysh[i*4+1], qy2 = ysh[i*4+2];
    float2 qp = pvsh[i];
    #pragma unroll
    for (int k = 0; k < 4; k++) {
      int e = eb * 4 + k;
      float4 c0 = *(const float4*)&csh[e * 8];
      float4 c1 = *(const float4*)&csh[e * 8 + 4];
      QTsh[e * 16 + qi] = c1.y + c0.x*qy0 + c0.y*qy1 + c0.z*qy2
                        + c0.w*qp.x + c1.x*qp.y;
    }
  }
  __syncthreads();

  int tj = t & 63, ig = t >> 6, warp = t >> 5;
  float4 yv[4];
  #pragma unroll
  for (int jl = 0; jl < 4; jl++)
    yv[jl] = *(const float4*)&ysh[(4 * tj + jl) * 4];
  float p2[4][3];
  #pragma unroll
  for (int ir = 0; ir < 4; ir++) { p2[ir][0]=0.f; p2[ir][1]=0.f; p2[ir][2]=0.f; }

  #pragma unroll
  for (int hh = 0; hh < 4; hh++) {
    if (hh == 2) {
      __syncthreads();
      #pragma unroll 4
      for (int e = 0; e < 32; e++) {     // half B: e = 32..63 (rows 96..127)
        float4 c0 = *(const float4*)&csh[(96 + e) * 8];
        float4 c1 = *(const float4*)&csh[(96 + e) * 8 + 4];
        KTsh[e * 256 + t] = c1.y + c0.x*y0 + c0.y*y1 + c0.z*y2v
                          + c0.w*ppt.x + c1.x*ppt.y;
      }
      __syncthreads();
    }
    int ebase = hh * 16;
    int krow  = (hh & 1) * 16;

    // packed accumulators: a2[ir][0] = {jl0, jl1}, a2[ir][1] = {jl2, jl3}
    unsigned long long a2[4][2];
    #pragma unroll
    for (int a = 0; a < 4; a++) { a2[a][0] = 0ull; a2[a][1] = 0ull; }

    #pragma unroll
    for (int d = 0; d < 16; d++) {
      const ulonglong2 kvp =
          *(const ulonglong2*)&KTsh[(krow + d) * 256 + 4 * tj];
      const float4 qv = *(const float4*)&QTsh[(ebase + d) * 16 + 4 * ig];
      unsigned long long q;
      PACKF2(q, qv.x);
      FFMA2(a2[0][0], q, kvp.x, a2[0][0]); FFMA2(a2[0][1], q, kvp.y, a2[0][1]);
      PACKF2(q, qv.y);
      FFMA2(a2[1][0], q, kvp.x, a2[1][0]); FFMA2(a2[1][1], q, kvp.y, a2[1][1]);
      PACKF2(q, qv.z);
      FFMA2(a2[2][0], q, kvp.x, a2[2][0]); FFMA2(a2[2][1], q, kvp.y, a2[2][1]);
      PACKF2(q, qv.w);
      FFMA2(a2[3][0], q, kvp.x, a2[3][0]); FFMA2(a2[3][1], q, kvp.y, a2[3][1]);
    }

    float acc[4][4];
    #pragma unroll
    for (int ir = 0; ir < 4; ir++) {
      UNPACKF2(acc[ir][0], acc[ir][1], a2[ir][0]);
      UNPACKF2(acc[ir][2], acc[ir][3], a2[ir][1]);
    }

    float sv[4];
    #pragma unroll
    for (int ir = 0; ir < 4; ir++) {
      float s = 0.f;
      #pragma unroll
      for (int jl = 0; jl < 4; jl++) {
        acc[ir][jl] = __expf(acc[ir][jl] * 0.25f);
        s += acc[ir][jl];
      }
      #pragma unroll
      for (int o = 16; o; o >>= 1)
        s += __shfl_xor_sync(0xffffffffu, s, o);
      sv[ir] = s;
    }
    if ((t & 31) == 0) {
      #pragma unroll
      for (int ir = 0; ir < 4; ir++) red[hh*32 + warp*4 + ir] = sv[ir];
    }
    __syncthreads();
    #pragma unroll
    for (int ir = 0; ir < 4; ir++)
      sv[ir] = 0.25f / (red[hh*32 + (ig*2)*4 + ir]
                      + red[hh*32 + (ig*2+1)*4 + ir]);

    #pragma unroll
    for (int ir = 0; ir < 4; ir++) {
      #pragma unroll
      for (int jl = 0; jl < 4; jl++) {
        float aw = acc[ir][jl] * sv[ir];
        p2[ir][0] += aw * yv[jl].x;
        p2[ir][1] += aw * yv[jl].y;
        p2[ir][2] += aw * yv[jl].z;
      }
    }
  }

  // ---- final reduction of p2 over the 64-group ----
  #pragma unroll
  for (int ir = 0; ir < 4; ir++)
    #pragma unroll
    for (int f = 0; f < 3; f++) {
      float v = p2[ir][f];
      #pragma unroll
      for (int o = 16; o; o >>= 1)
        v += __shfl_xor_sync(0xffffffffu, v, o);
      p2[ir][f] = v;
    }
  __syncthreads();
  if ((t & 31) == 0) {
    #pragma unroll
    for (int ir = 0; ir < 4; ir++)
      #pragma unroll
      for (int f = 0; f < 3; f++) red[warp * 16 + ir*3 + f] = p2[ir][f];
  }
  __syncthreads();
  if (tj == 0) {
    int w0 = (ig * 2) * 16, w1 = (ig * 2 + 1) * 16;
    #pragma unroll
    for (int ir = 0; ir < 4; ir++) {
      int i = i0 + ig * 4 + ir;
      #pragma unroll
      for (int f = 0; f < 3; f++)
        g_y2c[(f * Bz + b) * Pz + i] = red[w0 + ir*3 + f] + red[w1 + ir*3 + f];
    }
  }
}

// ---------------- kernel 4: interp + 50MB write (3 scalar planes) ----------
__global__ void __launch_bounds__(256) out_kernel(float* __restrict__ out) {
  __shared__ float y2sh[3][8 * 256];
  int t = threadIdx.x;
  int bg = blockIdx.y;          // batch group: 8 batches
  #pragma unroll
  for (int c = 0; c < 3; c++) {
    const float4* src = (const float4*)(g_y2c + (c * Bz + bg * 8) * Pz);
    #pragma unroll
    for (int k = 0; k < 2; k++)
      ((float4*)y2sh[c])[k * 256 + t] = src[k * 256 + t];
  }
  __syncthreads();

  int m = blockIdx.x * 256 + t;
  int4   ji = g_k2i[m];
  float4 wv = g_k2w[m];
  float w0 = wv.x, w1 = wv.y, w2 = wv.z;

  #pragma unroll
  for (int b = 0; b < 8; b++) {
    int o = b * 256;
    float r0 = w0*y2sh[0][o+ji.x] + w1*y2sh[0][o+ji.y] + w2*y2sh[0][o+ji.z];
    float r1 = w0*y2sh[1][o+ji.x] + w1*y2sh[1][o+ji.y] + w2*y2sh[1][o+ji.z];
    float r2 = w0*y2sh[2][o+ji.x] + w1*y2sh[2][o+ji.y] + w2*y2sh[2][o+ji.z];
    float* op = out + ((long)(bg * 8 + b) * NMz + m) * 3;
    op[0] = r0; op[1] = r1; op[2] = r2;
  }
}

// ---------------- launch ---------------------------------------------------
extern "C" void kernel_launch(void* const* d_in, const int* in_sizes, int n_in,
                              void* d_out, int out_size) {
  const float* node_attr = (const float*)d_in[0];
  const float* pos_mesh  = (const float*)d_in[1];
  const float* pos_piv   = (const float*)d_in[2];
  const float* gamma     = (const float*)d_in[3];
  const float* beta      = (const float*)d_in[4];
  const float* Wf        = (const float*)d_in[5];
  const float* bf        = (const float*)d_in[6];
  const float* Wp        = (const float*)d_in[7];
  const float* bp        = (const float*)d_in[8];
  const float* inW       = (const float*)d_in[9];
  const float* inB       = (const float*)d_in[10];
  float* out = (float*)d_out;

  const int SMEM_KNN = CHSZ * 8 + 2 * 3072;        // 38,912 B
  cudaFuncSetAttribute(knn_all,
      cudaFuncAttributeMaxDynamicSharedMemorySize, SMEM_KNN);

  knn_all<<<769, 256, SMEM_KNN>>>(pos_mesh, pos_piv,
                                  Wf, bf, Wp, bp, inW, inB);
  merge_kernel<<<1, 256>>>();
  attn_kernel<<<512, 256>>>(pos_piv, node_attr, gamma, beta);
  out_kernel<<<dim3(NMz / 256, 4), 256>>>(out);
}